// round 3
// baseline (speedup 1.0000x reference)
#include <cuda_runtime.h>
#include <cstdint>

#define N_NODES   100000
#define N_EDGES   1600000
#define IN_FEATS  128
#define OUT_FEATS 256
#define TOPK      32

// Scratch (allocation-free rule: __device__ globals)
__device__ float g_xsparse[(size_t)N_NODES * IN_FEATS];
__device__ float g_agg    [(size_t)N_NODES * IN_FEATS];

// ---------------------------------------------------------------------------
// Kernel 1: scatter top-k values into dense x_sparse rows, zero agg rows.
// One warp per node row. Shared-mem row buffer + shared atomicAdd handles
// duplicate indices exactly like the reference's .add scatter.
// ---------------------------------------------------------------------------
__global__ void scatter_topk_kernel(const float* __restrict__ topk_values,
                                    const int*   __restrict__ topk_indices,
                                    float* __restrict__ xsparse,
                                    float* __restrict__ agg) {
    __shared__ float srow[8][IN_FEATS];
    const int warp = threadIdx.x >> 5;
    const int lane = threadIdx.x & 31;
    const int row  = blockIdx.x * 8 + warp;
    if (row >= N_NODES) return;

    const float4 z = make_float4(0.f, 0.f, 0.f, 0.f);
    ((float4*)srow[warp])[lane] = z;            // 32 lanes x 16B = 128 floats
    __syncwarp();

    const int   idx = topk_indices[(size_t)row * TOPK + lane];
    const float val = topk_values [(size_t)row * TOPK + lane];
    atomicAdd(&srow[warp][idx], val);
    __syncwarp();

    ((float4*)(xsparse + (size_t)row * IN_FEATS))[lane] = ((float4*)srow[warp])[lane];
    ((float4*)(agg     + (size_t)row * IN_FEATS))[lane] = z;
}

// ---------------------------------------------------------------------------
// Kernel 2: SpMM (mean aggregation). Rows are sorted, so each warp walks a
// contiguous 128-edge chunk, accumulating a float4 per lane in registers and
// flushing with atomicAdd only on row transitions / chunk boundaries.
// The 1/degree normalization is folded into the flush (linear in the sum).
// ---------------------------------------------------------------------------
#define EDGES_PER_WARP 128

__global__ void spmm_kernel(const int*   __restrict__ row,
                            const int*   __restrict__ col,
                            const float* __restrict__ degrees,
                            const float* __restrict__ xsparse,
                            float* __restrict__ agg) {
    const int gwarp = (blockIdx.x * blockDim.x + threadIdx.x) >> 5;
    const int lane  = threadIdx.x & 31;
    const long e0 = (long)gwarp * EDGES_PER_WARP;
    if (e0 >= N_EDGES) return;
    const long e1 = min(e0 + (long)EDGES_PER_WARP, (long)N_EDGES);

    float4 acc = make_float4(0.f, 0.f, 0.f, 0.f);
    int cur = __ldg(row + e0);

    for (long e = e0; e < e1; ++e) {
        const int r = __ldg(row + e);
        const int c = __ldg(col + e);
        if (r != cur) {
            const float inv = 1.0f / degrees[cur];
            float* dst = agg + (size_t)cur * IN_FEATS + lane * 4;
            atomicAdd(dst + 0, acc.x * inv);
            atomicAdd(dst + 1, acc.y * inv);
            atomicAdd(dst + 2, acc.z * inv);
            atomicAdd(dst + 3, acc.w * inv);
            acc = make_float4(0.f, 0.f, 0.f, 0.f);
            cur = r;
        }
        const float4 v = *(const float4*)(xsparse + (size_t)c * IN_FEATS + lane * 4);
        acc.x += v.x; acc.y += v.y; acc.z += v.z; acc.w += v.w;
    }
    const float inv = 1.0f / degrees[cur];
    float* dst = agg + (size_t)cur * IN_FEATS + lane * 4;
    atomicAdd(dst + 0, acc.x * inv);
    atomicAdd(dst + 1, acc.y * inv);
    atomicAdd(dst + 2, acc.z * inv);
    atomicAdd(dst + 3, acc.w * inv);
}

// ---------------------------------------------------------------------------
// Kernel 3: fused GEMM  out = [agg | feat] @ [W_neigh ; W_self] + b_self
// Virtual K = 256. Tiled fp32: BM=BN=64, BK=32, 256 threads, 4x4 per thread.
// ---------------------------------------------------------------------------
#define BM 64
#define BN 64
#define BK 32

__global__ __launch_bounds__(256)
void fused_gemm_kernel(const float* __restrict__ agg,
                       const float* __restrict__ feat,
                       const float* __restrict__ Wn,
                       const float* __restrict__ Ws,
                       const float* __restrict__ bias,
                       float* __restrict__ out) {
    __shared__ float As[BM][BK + 1];
    __shared__ float Bs[BK][BN];

    const int tx = threadIdx.x & 15;       // 0..15  -> 4 cols each
    const int ty = threadIdx.x >> 4;       // 0..15  -> 4 rows each
    const int rowBase = blockIdx.y * BM;
    const int colBase = blockIdx.x * BN;

    float acc[4][4] = {};

    #pragma unroll 1
    for (int t = 0; t < (2 * IN_FEATS) / BK; ++t) {
        const int k0 = t * BK;

        // Load A tile (64 x 32): virtual A = [agg | feat]
        #pragma unroll
        for (int i = 0; i < (BM * BK) / 256; ++i) {
            const int li = threadIdx.x + i * 256;
            const int m = li >> 5, k = li & 31;
            const int gm = rowBase + m, gk = k0 + k;
            float v = 0.f;
            if (gm < N_NODES) {
                v = (gk < IN_FEATS) ? agg [(size_t)gm * IN_FEATS + gk]
                                    : feat[(size_t)gm * IN_FEATS + (gk - IN_FEATS)];
            }
            As[m][k] = v;
        }
        // Load B tile (32 x 64): virtual B = [Wn ; Ws]
        #pragma unroll
        for (int i = 0; i < (BK * BN) / 256; ++i) {
            const int li = threadIdx.x + i * 256;
            const int k = li >> 6, n = li & 63;
            const int gk = k0 + k;
            Bs[k][n] = (gk < IN_FEATS) ? Wn[(size_t)gk * OUT_FEATS + colBase + n]
                                       : Ws[(size_t)(gk - IN_FEATS) * OUT_FEATS + colBase + n];
        }
        __syncthreads();

        #pragma unroll
        for (int kk = 0; kk < BK; ++kk) {
            const float a0 = As[ty * 4 + 0][kk];
            const float a1 = As[ty * 4 + 1][kk];
            const float a2 = As[ty * 4 + 2][kk];
            const float a3 = As[ty * 4 + 3][kk];
            const float4 b4 = *(const float4*)&Bs[kk][tx * 4];
            acc[0][0] += a0 * b4.x; acc[0][1] += a0 * b4.y; acc[0][2] += a0 * b4.z; acc[0][3] += a0 * b4.w;
            acc[1][0] += a1 * b4.x; acc[1][1] += a1 * b4.y; acc[1][2] += a1 * b4.z; acc[1][3] += a1 * b4.w;
            acc[2][0] += a2 * b4.x; acc[2][1] += a2 * b4.y; acc[2][2] += a2 * b4.z; acc[2][3] += a2 * b4.w;
            acc[3][0] += a3 * b4.x; acc[3][1] += a3 * b4.y; acc[3][2] += a3 * b4.z; acc[3][3] += a3 * b4.w;
        }
        __syncthreads();
    }

    #pragma unroll
    for (int i = 0; i < 4; ++i) {
        const int gm = rowBase + ty * 4 + i;
        if (gm >= N_NODES) continue;
        #pragma unroll
        for (int j = 0; j < 4; ++j) {
            const int gn = colBase + tx * 4 + j;
            out[(size_t)gm * OUT_FEATS + gn] = acc[i][j] + bias[gn];
        }
    }
}

// ---------------------------------------------------------------------------
extern "C" void kernel_launch(void* const* d_in, const int* in_sizes, int n_in,
                              void* d_out, int out_size) {
    const float* feat    = (const float*)d_in[0];
    const float* topk_v  = (const float*)d_in[1];
    const int*   topk_i  = (const int*)  d_in[2];
    const int*   row     = (const int*)  d_in[3];
    const int*   col     = (const int*)  d_in[4];
    const float* degrees = (const float*)d_in[5];
    const float* Wn      = (const float*)d_in[6];
    const float* Ws      = (const float*)d_in[7];
    const float* bias    = (const float*)d_in[8];
    float*       out     = (float*)d_out;

    float* xsparse;
    float* agg;
    cudaGetSymbolAddress((void**)&xsparse, g_xsparse);
    cudaGetSymbolAddress((void**)&agg,     g_agg);

    // 1) scatter top-k -> dense rows, zero agg
    {
        const int blocks = (N_NODES + 7) / 8;
        scatter_topk_kernel<<<blocks, 256>>>(topk_v, topk_i, xsparse, agg);
    }
    // 2) warp-segmented SpMM with mean normalization
    {
        const int warps  = (N_EDGES + EDGES_PER_WARP - 1) / EDGES_PER_WARP;
        const int blocks = (warps + 7) / 8;
        spmm_kernel<<<blocks, 256>>>(row, col, degrees, xsparse, agg);
    }
    // 3) fused dual GEMM + bias
    {
        dim3 grid(OUT_FEATS / BN, (N_NODES + BM - 1) / BM);
        fused_gemm_kernel<<<grid, 256>>>(agg, feat, Wn, Ws, bias, out);
    }
}

// round 4
// speedup vs baseline: 1.0130x; 1.0130x over previous
#include <cuda_runtime.h>
#include <cstdint>

#define N_NODES   100000
#define N_EDGES   1600000
#define IN_FEATS  128
#define OUT_FEATS 256
#define TOPK      32

// Scratch (allocation-free rule: __device__ globals)
__device__ float g_xsparse[(size_t)N_NODES * IN_FEATS];
__device__ float g_agg    [(size_t)N_NODES * IN_FEATS];

// ---------------------------------------------------------------------------
// Kernel 1: scatter top-k values into dense x_sparse rows, zero agg rows.
// One warp per node row. Shared-mem row buffer + shared atomicAdd handles
// duplicate indices exactly like the reference's .add scatter.
// ---------------------------------------------------------------------------
__global__ void scatter_topk_kernel(const float* __restrict__ topk_values,
                                    const int*   __restrict__ topk_indices,
                                    float* __restrict__ xsparse,
                                    float* __restrict__ agg) {
    __shared__ float srow[8][IN_FEATS];
    const int warp = threadIdx.x >> 5;
    const int lane = threadIdx.x & 31;
    const int row  = blockIdx.x * 8 + warp;
    if (row >= N_NODES) return;

    const float4 z = make_float4(0.f, 0.f, 0.f, 0.f);
    ((float4*)srow[warp])[lane] = z;            // 32 lanes x 16B = 128 floats
    __syncwarp();

    const int   idx = topk_indices[(size_t)row * TOPK + lane];
    const float val = topk_values [(size_t)row * TOPK + lane];
    atomicAdd(&srow[warp][idx], val);
    __syncwarp();

    ((float4*)(xsparse + (size_t)row * IN_FEATS))[lane] = ((float4*)srow[warp])[lane];
    ((float4*)(agg     + (size_t)row * IN_FEATS))[lane] = z;
}

// ---------------------------------------------------------------------------
// Kernel 2: SpMM (mean aggregation). Rows are sorted, so each warp walks a
// contiguous 128-edge chunk, accumulating a float4 per lane in registers and
// flushing with atomicAdd only on row transitions / chunk boundaries.
// The 1/degree normalization is folded into the flush (linear in the sum).
// ---------------------------------------------------------------------------
#define EDGES_PER_WARP 128

__global__ void spmm_kernel(const int*   __restrict__ row,
                            const int*   __restrict__ col,
                            const float* __restrict__ degrees,
                            const float* __restrict__ xsparse,
                            float* __restrict__ agg) {
    const int gwarp = (blockIdx.x * blockDim.x + threadIdx.x) >> 5;
    const int lane  = threadIdx.x & 31;
    const long e0 = (long)gwarp * EDGES_PER_WARP;
    if (e0 >= N_EDGES) return;
    const long e1 = min(e0 + (long)EDGES_PER_WARP, (long)N_EDGES);

    float4 acc = make_float4(0.f, 0.f, 0.f, 0.f);
    int cur = __ldg(row + e0);

    for (long e = e0; e < e1; ++e) {
        const int r = __ldg(row + e);
        const int c = __ldg(col + e);
        if (r != cur) {
            const float inv = 1.0f / degrees[cur];
            float* dst = agg + (size_t)cur * IN_FEATS + lane * 4;
            atomicAdd(dst + 0, acc.x * inv);
            atomicAdd(dst + 1, acc.y * inv);
            atomicAdd(dst + 2, acc.z * inv);
            atomicAdd(dst + 3, acc.w * inv);
            acc = make_float4(0.f, 0.f, 0.f, 0.f);
            cur = r;
        }
        const float4 v = *(const float4*)(xsparse + (size_t)c * IN_FEATS + lane * 4);
        acc.x += v.x; acc.y += v.y; acc.z += v.z; acc.w += v.w;
    }
    const float inv = 1.0f / degrees[cur];
    float* dst = agg + (size_t)cur * IN_FEATS + lane * 4;
    atomicAdd(dst + 0, acc.x * inv);
    atomicAdd(dst + 1, acc.y * inv);
    atomicAdd(dst + 2, acc.z * inv);
    atomicAdd(dst + 3, acc.w * inv);
}

// ---------------------------------------------------------------------------
// Kernel 3: fused GEMM  out = [agg | feat] @ [W_neigh ; W_self] + b_self
// Virtual K = 256. Tiled fp32: BM=BN=64, BK=32, 256 threads, 4x4 per thread.
// ---------------------------------------------------------------------------
#define BM 64
#define BN 64
#define BK 32

__global__ __launch_bounds__(256)
void fused_gemm_kernel(const float* __restrict__ agg,
                       const float* __restrict__ feat,
                       const float* __restrict__ Wn,
                       const float* __restrict__ Ws,
                       const float* __restrict__ bias,
                       float* __restrict__ out) {
    __shared__ float As[BM][BK + 1];
    __shared__ float Bs[BK][BN];

    const int tx = threadIdx.x & 15;       // 0..15  -> 4 cols each
    const int ty = threadIdx.x >> 4;       // 0..15  -> 4 rows each
    const int rowBase = blockIdx.y * BM;
    const int colBase = blockIdx.x * BN;

    float acc[4][4] = {};

    #pragma unroll 1
    for (int t = 0; t < (2 * IN_FEATS) / BK; ++t) {
        const int k0 = t * BK;

        // Load A tile (64 x 32): virtual A = [agg | feat]
        #pragma unroll
        for (int i = 0; i < (BM * BK) / 256; ++i) {
            const int li = threadIdx.x + i * 256;
            const int m = li >> 5, k = li & 31;
            const int gm = rowBase + m, gk = k0 + k;
            float v = 0.f;
            if (gm < N_NODES) {
                v = (gk < IN_FEATS) ? agg [(size_t)gm * IN_FEATS + gk]
                                    : feat[(size_t)gm * IN_FEATS + (gk - IN_FEATS)];
            }
            As[m][k] = v;
        }
        // Load B tile (32 x 64): virtual B = [Wn ; Ws]
        #pragma unroll
        for (int i = 0; i < (BK * BN) / 256; ++i) {
            const int li = threadIdx.x + i * 256;
            const int k = li >> 6, n = li & 63;
            const int gk = k0 + k;
            Bs[k][n] = (gk < IN_FEATS) ? Wn[(size_t)gk * OUT_FEATS + colBase + n]
                                       : Ws[(size_t)(gk - IN_FEATS) * OUT_FEATS + colBase + n];
        }
        __syncthreads();

        #pragma unroll
        for (int kk = 0; kk < BK; ++kk) {
            const float a0 = As[ty * 4 + 0][kk];
            const float a1 = As[ty * 4 + 1][kk];
            const float a2 = As[ty * 4 + 2][kk];
            const float a3 = As[ty * 4 + 3][kk];
            const float4 b4 = *(const float4*)&Bs[kk][tx * 4];
            acc[0][0] += a0 * b4.x; acc[0][1] += a0 * b4.y; acc[0][2] += a0 * b4.z; acc[0][3] += a0 * b4.w;
            acc[1][0] += a1 * b4.x; acc[1][1] += a1 * b4.y; acc[1][2] += a1 * b4.z; acc[1][3] += a1 * b4.w;
            acc[2][0] += a2 * b4.x; acc[2][1] += a2 * b4.y; acc[2][2] += a2 * b4.z; acc[2][3] += a2 * b4.w;
            acc[3][0] += a3 * b4.x; acc[3][1] += a3 * b4.y; acc[3][2] += a3 * b4.z; acc[3][3] += a3 * b4.w;
        }
        __syncthreads();
    }

    #pragma unroll
    for (int i = 0; i < 4; ++i) {
        const int gm = rowBase + ty * 4 + i;
        if (gm >= N_NODES) continue;
        #pragma unroll
        for (int j = 0; j < 4; ++j) {
            const int gn = colBase + tx * 4 + j;
            out[(size_t)gm * OUT_FEATS + gn] = acc[i][j] + bias[gn];
        }
    }
}

// ---------------------------------------------------------------------------
extern "C" void kernel_launch(void* const* d_in, const int* in_sizes, int n_in,
                              void* d_out, int out_size) {
    const float* feat    = (const float*)d_in[0];
    const float* topk_v  = (const float*)d_in[1];
    const int*   topk_i  = (const int*)  d_in[2];
    const int*   row     = (const int*)  d_in[3];
    const int*   col     = (const int*)  d_in[4];
    const float* degrees = (const float*)d_in[5];
    const float* Wn      = (const float*)d_in[6];
    const float* Ws      = (const float*)d_in[7];
    const float* bias    = (const float*)d_in[8];
    float*       out     = (float*)d_out;

    float* xsparse;
    float* agg;
    cudaGetSymbolAddress((void**)&xsparse, g_xsparse);
    cudaGetSymbolAddress((void**)&agg,     g_agg);

    // 1) scatter top-k -> dense rows, zero agg
    {
        const int blocks = (N_NODES + 7) / 8;
        scatter_topk_kernel<<<blocks, 256>>>(topk_v, topk_i, xsparse, agg);
    }
    // 2) warp-segmented SpMM with mean normalization
    {
        const int warps  = (N_EDGES + EDGES_PER_WARP - 1) / EDGES_PER_WARP;
        const int blocks = (warps + 7) / 8;
        spmm_kernel<<<blocks, 256>>>(row, col, degrees, xsparse, agg);
    }
    // 3) fused dual GEMM + bias
    {
        dim3 grid(OUT_FEATS / BN, (N_NODES + BM - 1) / BM);
        fused_gemm_kernel<<<grid, 256>>>(agg, feat, Wn, Ws, bias, out);
    }
}

// round 6
// speedup vs baseline: 1.9894x; 1.9638x over previous
#include <cuda_runtime.h>
#include <cuda_bf16.h>
#include <cstdint>

#define N_NODES   100000
#define N_EDGES   1600000
#define IN_FEATS  128
#define OUT_FEATS 256
#define TOPK      32

// Scratch (allocation-free rule: __device__ globals)
__device__ float g_xsparse[(size_t)N_NODES * IN_FEATS];
__device__ float g_agg    [(size_t)N_NODES * IN_FEATS];

// ---------------------------------------------------------------------------
// Kernel 1: scatter top-k values into dense x_sparse rows, zero agg rows.
// ---------------------------------------------------------------------------
__global__ void scatter_topk_kernel(const float* __restrict__ topk_values,
                                    const int*   __restrict__ topk_indices,
                                    float* __restrict__ xsparse,
                                    float* __restrict__ agg) {
    __shared__ float srow[8][IN_FEATS];
    const int warp = threadIdx.x >> 5;
    const int lane = threadIdx.x & 31;
    const int row  = blockIdx.x * 8 + warp;
    if (row >= N_NODES) return;

    const float4 z = make_float4(0.f, 0.f, 0.f, 0.f);
    ((float4*)srow[warp])[lane] = z;
    __syncwarp();

    const int   idx = topk_indices[(size_t)row * TOPK + lane];
    const float val = topk_values [(size_t)row * TOPK + lane];
    atomicAdd(&srow[warp][idx], val);
    __syncwarp();

    ((float4*)(xsparse + (size_t)row * IN_FEATS))[lane] = ((float4*)srow[warp])[lane];
    ((float4*)(agg     + (size_t)row * IN_FEATS))[lane] = z;
}

// ---------------------------------------------------------------------------
// Kernel 2: warp-segmented SpMM (mean aggregation), rows sorted.
// ---------------------------------------------------------------------------
#define EDGES_PER_WARP 128

__global__ void spmm_kernel(const int*   __restrict__ row,
                            const int*   __restrict__ col,
                            const float* __restrict__ degrees,
                            const float* __restrict__ xsparse,
                            float* __restrict__ agg) {
    const int gwarp = (blockIdx.x * blockDim.x + threadIdx.x) >> 5;
    const int lane  = threadIdx.x & 31;
    const long e0 = (long)gwarp * EDGES_PER_WARP;
    if (e0 >= N_EDGES) return;
    const long e1 = min(e0 + (long)EDGES_PER_WARP, (long)N_EDGES);

    float4 acc = make_float4(0.f, 0.f, 0.f, 0.f);
    int cur = __ldg(row + e0);

    for (long e = e0; e < e1; ++e) {
        const int r = __ldg(row + e);
        const int c = __ldg(col + e);
        if (r != cur) {
            const float inv = 1.0f / degrees[cur];
            float* dst = agg + (size_t)cur * IN_FEATS + lane * 4;
            atomicAdd(dst + 0, acc.x * inv);
            atomicAdd(dst + 1, acc.y * inv);
            atomicAdd(dst + 2, acc.z * inv);
            atomicAdd(dst + 3, acc.w * inv);
            acc = make_float4(0.f, 0.f, 0.f, 0.f);
            cur = r;
        }
        const float4 v = *(const float4*)(xsparse + (size_t)c * IN_FEATS + lane * 4);
        acc.x += v.x; acc.y += v.y; acc.z += v.z; acc.w += v.w;
    }
    const float inv = 1.0f / degrees[cur];
    float* dst = agg + (size_t)cur * IN_FEATS + lane * 4;
    atomicAdd(dst + 0, acc.x * inv);
    atomicAdd(dst + 1, acc.y * inv);
    atomicAdd(dst + 2, acc.z * inv);
    atomicAdd(dst + 3, acc.w * inv);
}

// ---------------------------------------------------------------------------
// Kernel 3: tensor-core fused GEMM (bf16 3-term split, fp32 accumulate)
//   out = [agg | feat] (M x 256) @ [Wn ; Ws] (256 x 256) + bias
// BM=BN=128, BK=16, 256 threads (8 warps, 4x2), warp tile 32x64.
// mma.sync.m16n8k16.bf16: per iter per warp 2 m-frags x 8 n-frags x 3 terms.
// ---------------------------------------------------------------------------
#define GBM 128
#define GBN 128
#define GBK 16
#define ASTR 12   // __nv_bfloat162 stride per row (8 used + 4 pad): conflict-free frag reads
#define BSTR 12

#define MMA_BF16(d, a0, a1, a2, a3, b0, b1)                                   \
    asm volatile("mma.sync.aligned.m16n8k16.row.col.f32.bf16.bf16.f32 "        \
                 "{%0,%1,%2,%3}, {%4,%5,%6,%7}, {%8,%9}, {%0,%1,%2,%3};"        \
                 : "+f"(d[0]), "+f"(d[1]), "+f"(d[2]), "+f"(d[3])              \
                 : "r"(a0), "r"(a1), "r"(a2), "r"(a3), "r"(b0), "r"(b1))

__device__ __forceinline__ void split2(float x, float y,
                                       __nv_bfloat162& hi, __nv_bfloat162& lo) {
    const __nv_bfloat16 hx = __float2bfloat16_rn(x);
    const __nv_bfloat16 hy = __float2bfloat16_rn(y);
    const __nv_bfloat16 lx = __float2bfloat16_rn(x - __bfloat162float(hx));
    const __nv_bfloat16 ly = __float2bfloat16_rn(y - __bfloat162float(hy));
    hi = __halves2bfloat162(hx, hy);   // .x = even-k element
    lo = __halves2bfloat162(lx, ly);
}

__global__ __launch_bounds__(256)
void mma_gemm_kernel(const float* __restrict__ agg,
                     const float* __restrict__ feat,
                     const float* __restrict__ Wn,
                     const float* __restrict__ Ws,
                     const float* __restrict__ bias,
                     float* __restrict__ out) {
    __shared__ __nv_bfloat162 As_hi[GBM][ASTR];
    __shared__ __nv_bfloat162 As_lo[GBM][ASTR];
    __shared__ __nv_bfloat162 Bs_hi[GBN][BSTR];
    __shared__ __nv_bfloat162 Bs_lo[GBN][BSTR];

    const int tid  = threadIdx.x;
    const int lane = tid & 31;
    const int warp = tid >> 5;
    const int wm   = warp >> 1;     // 0..3 (M)
    const int wn   = warp & 1;      // 0..1 (N)
    const int g    = lane >> 2;     // 0..7
    const int c    = lane & 3;      // 0..3
    const int rowBase = blockIdx.y * GBM;
    const int colBase = blockIdx.x * GBN;

    float acc[2][8][4];
    #pragma unroll
    for (int i = 0; i < 2; ++i)
        #pragma unroll
        for (int j = 0; j < 8; ++j)
            #pragma unroll
            for (int q = 0; q < 4; ++q) acc[i][j][q] = 0.f;

    // A-load mapping: thread -> row am (0..127), two float4 per iter
    const int am = tid >> 1;
    const int af = tid & 1;
    // B-load mapping: thread -> col bn (0..127), four k2 per iter
    const int bn  = tid & 127;
    const int bkh = (tid >> 7) * 4;
    const int bxr = (bn >> 3) & 3;   // xor-swizzle key for B store

    float4 aR[2];
    float  bR[8];

    auto loadA = [&](int t) {
        const int k0 = t * GBK;
        #pragma unroll
        for (int it = 0; it < 2; ++it) {
            const int f4 = af + 2 * it;
            const int gm = rowBase + am;
            const int gk = k0 + f4 * 4;
            float4 v = make_float4(0.f, 0.f, 0.f, 0.f);
            if (gm < N_NODES) {
                const float* src = (gk < IN_FEATS)
                    ? (agg  + (size_t)gm * IN_FEATS + gk)
                    : (feat + (size_t)gm * IN_FEATS + (gk - IN_FEATS));
                v = *(const float4*)src;
            }
            aR[it] = v;
        }
    };
    auto loadB = [&](int t) {
        const int k0 = t * GBK;
        #pragma unroll
        for (int j = 0; j < 4; ++j) {
            const int gk = k0 + 2 * (bkh + j);
            const float* src = (gk < IN_FEATS)
                ? (Wn + (size_t)gk * OUT_FEATS)
                : (Ws + (size_t)(gk - IN_FEATS) * OUT_FEATS);
            bR[2 * j]     = src[colBase + bn];
            bR[2 * j + 1] = src[OUT_FEATS + colBase + bn];
        }
    };
    auto stage = [&]() {
        #pragma unroll
        for (int it = 0; it < 2; ++it) {
            const int f4 = af + 2 * it;
            __nv_bfloat162 h, l;
            split2(aR[it].x, aR[it].y, h, l);
            As_hi[am][f4 * 2] = h;  As_lo[am][f4 * 2] = l;
            split2(aR[it].z, aR[it].w, h, l);
            As_hi[am][f4 * 2 + 1] = h;  As_lo[am][f4 * 2 + 1] = l;
        }
        #pragma unroll
        for (int j = 0; j < 4; ++j) {
            const int k2 = bkh + j;
            __nv_bfloat162 h, l;
            split2(bR[2 * j], bR[2 * j + 1], h, l);
            Bs_hi[bn][k2 ^ bxr] = h;
            Bs_lo[bn][k2 ^ bxr] = l;
        }
    };

    loadA(0); loadB(0);

    #pragma unroll 1
    for (int t = 0; t < (2 * IN_FEATS) / GBK; ++t) {
        stage();
        __syncthreads();
        if (t < (2 * IN_FEATS) / GBK - 1) { loadA(t + 1); loadB(t + 1); }

        // A fragments (hi & lo), 2 m-frags
        uint32_t ahi[2][4], alo[2][4];
        #pragma unroll
        for (int i = 0; i < 2; ++i) {
            const int r0 = wm * 32 + i * 16 + g;
            ahi[i][0] = *(const uint32_t*)&As_hi[r0    ][c];
            ahi[i][1] = *(const uint32_t*)&As_hi[r0 + 8][c];
            ahi[i][2] = *(const uint32_t*)&As_hi[r0    ][c + 4];
            ahi[i][3] = *(const uint32_t*)&As_hi[r0 + 8][c + 4];
            alo[i][0] = *(const uint32_t*)&As_lo[r0    ][c];
            alo[i][1] = *(const uint32_t*)&As_lo[r0 + 8][c];
            alo[i][2] = *(const uint32_t*)&As_lo[r0    ][c + 4];
            alo[i][3] = *(const uint32_t*)&As_lo[r0 + 8][c + 4];
        }
        #pragma unroll
        for (int j = 0; j < 8; ++j) {
            const int n  = wn * 64 + j * 8 + g;
            const int xr = (n >> 3) & 3;            // uniform per (warp, j)
            const uint32_t bh0 = *(const uint32_t*)&Bs_hi[n][c ^ xr];
            const uint32_t bh1 = *(const uint32_t*)&Bs_hi[n][(c + 4) ^ xr];
            const uint32_t bl0 = *(const uint32_t*)&Bs_lo[n][c ^ xr];
            const uint32_t bl1 = *(const uint32_t*)&Bs_lo[n][(c + 4) ^ xr];
            #pragma unroll
            for (int i = 0; i < 2; ++i) {
                MMA_BF16(acc[i][j], ahi[i][0], ahi[i][1], ahi[i][2], ahi[i][3], bh0, bh1);
                MMA_BF16(acc[i][j], alo[i][0], alo[i][1], alo[i][2], alo[i][3], bh0, bh1);
                MMA_BF16(acc[i][j], ahi[i][0], ahi[i][1], ahi[i][2], ahi[i][3], bl0, bl1);
            }
        }
        __syncthreads();
    }

    // Epilogue: bias + store (float2 per fragment half)
    #pragma unroll
    for (int i = 0; i < 2; ++i) {
        const int r0 = rowBase + wm * 32 + i * 16 + g;
        #pragma unroll
        for (int j = 0; j < 8; ++j) {
            const int n0 = colBase + wn * 64 + j * 8 + 2 * c;
            const float b0 = bias[n0];
            const float b1 = bias[n0 + 1];
            if (r0 < N_NODES) {
                float2 v = make_float2(acc[i][j][0] + b0, acc[i][j][1] + b1);
                *(float2*)(out + (size_t)r0 * OUT_FEATS + n0) = v;
            }
            if (r0 + 8 < N_NODES) {
                float2 v = make_float2(acc[i][j][2] + b0, acc[i][j][3] + b1);
                *(float2*)(out + (size_t)(r0 + 8) * OUT_FEATS + n0) = v;
            }
        }
    }
}

// ---------------------------------------------------------------------------
extern "C" void kernel_launch(void* const* d_in, const int* in_sizes, int n_in,
                              void* d_out, int out_size) {
    const float* feat    = (const float*)d_in[0];
    const float* topk_v  = (const float*)d_in[1];
    const int*   topk_i  = (const int*)  d_in[2];
    const int*   row     = (const int*)  d_in[3];
    const int*   col     = (const int*)  d_in[4];
    const float* degrees = (const float*)d_in[5];
    const float* Wn      = (const float*)d_in[6];
    const float* Ws      = (const float*)d_in[7];
    const float* bias    = (const float*)d_in[8];
    float*       out     = (float*)d_out;

    float* xsparse;
    float* agg;
    cudaGetSymbolAddress((void**)&xsparse, g_xsparse);
    cudaGetSymbolAddress((void**)&agg,     g_agg);

    // 1) scatter top-k -> dense rows, zero agg
    {
        const int blocks = (N_NODES + 7) / 8;
        scatter_topk_kernel<<<blocks, 256>>>(topk_v, topk_i, xsparse, agg);
    }
    // 2) warp-segmented SpMM with mean normalization
    {
        const int warps  = (N_EDGES + EDGES_PER_WARP - 1) / EDGES_PER_WARP;
        const int blocks = (warps + 7) / 8;
        spmm_kernel<<<blocks, 256>>>(row, col, degrees, xsparse, agg);
    }
    // 3) tensor-core fused dual GEMM + bias
    {
        dim3 grid(OUT_FEATS / GBN, (N_NODES + GBM - 1) / GBM);
        mma_gemm_kernel<<<grid, 256>>>(agg, feat, Wn, Ws, bias, out);
    }
}